// round 6
// baseline (speedup 1.0000x reference)
#include <cuda_runtime.h>

#define NN 1024
#define BN 4096
#define NH 8
#define TI 32
#define TJ 32

typedef unsigned long long ull;

// ---- scratch ----
__device__ float g_V[BN*128];
__device__ float g_SKIP[BN*128];
__device__ float g_A1[BN*NH];
__device__ float g_A2[BN*NH];
__device__ float g_ATTG[4*NH];

// ---- packed f32x2 helpers ----
__device__ __forceinline__ ull ffma2(ull a, ull b, ull c) {
    ull d; asm("fma.rn.f32x2 %0,%1,%2,%3;" : "=l"(d) : "l"(a), "l"(b), "l"(c)); return d;
}
__device__ __forceinline__ ull fadd2(ull a, ull b) {
    ull d; asm("add.rn.f32x2 %0,%1,%2;" : "=l"(d) : "l"(a), "l"(b)); return d;
}
__device__ __forceinline__ ull fsub2(ull a, ull b) {
    ull d; asm("sub.rn.f32x2 %0,%1,%2;" : "=l"(d) : "l"(a), "l"(b)); return d;
}
__device__ __forceinline__ ull fmul2(ull a, ull b) {
    ull d; asm("mul.rn.f32x2 %0,%1,%2;" : "=l"(d) : "l"(a), "l"(b)); return d;
}
__device__ __forceinline__ ull pack2(float x, float y) {
    ull r; asm("mov.b64 %0,{%1,%2};" : "=l"(r) : "f"(x), "f"(y)); return r;
}
__device__ __forceinline__ float2 unpack2(ull v) {
    float2 r; asm("mov.b64 {%0,%1},%2;" : "=f"(r.x), "=f"(r.y) : "l"(v)); return r;
}
__device__ __forceinline__ ull shflx2(ull v, int m) {
    unsigned lo = (unsigned)v, hi = (unsigned)(v >> 32);
    lo = __shfl_xor_sync(0xffffffffu, lo, m);
    hi = __shfl_xor_sync(0xffffffffu, hi, m);
    return ((ull)hi << 32) | (ull)lo;
}

// ---- cp.async ----
__device__ __forceinline__ void cpa16(unsigned dst, const void* src) {
    asm volatile("cp.async.cg.shared.global [%0], [%1], 16;" :: "r"(dst), "l"(src));
}
__device__ __forceinline__ void cp_commit() {
    asm volatile("cp.async.commit_group;" ::: "memory");
}
__device__ __forceinline__ void cp_wait0() {
    asm volatile("cp.async.wait_group 0;" ::: "memory");
}

// ---- smem layout (float words) ----
#define EDGE_OFF(buf) ((buf) ? 16512 : 0)       // 2 x 16512 (i stride 516)
#define VALS_OFF(buf) ((buf) ? 38144 : 33024)   // 2 x 5120  (h*640 + j*20 + d)
#define T_OFF         43264                      // 9728 ([h]1216 [ip]76 [io]36 [j])
#define ADJ_OFF(buf)  ((buf) ? 54144 : 52992)   // 2 x 1152  (i stride 36, ints)
#define A2_OFF(buf)   ((buf) ? 55552 : 55296)   // 2 x 256   (j*8 + h)
#define SMEM_WORDS    55808                      // 223232 bytes

// =====================================================================
// Kernel A: per-node GEMMs (same as R5: 16 rows/block, 3 blk/SM).
// =====================================================================
#define ZSTR 260
__global__ __launch_bounds__(256, 3) void gat_prep(
    const float* __restrict__ node, const float* __restrict__ hidden,
    const float* __restrict__ m_w,  const float* __restrict__ m_b,
    const float* __restrict__ skip_w, const float* __restrict__ skip_b,
    const float* __restrict__ a1_w, const float* __restrict__ a1_b,
    const float* __restrict__ a2_w, const float* __restrict__ a2_b,
    const float* __restrict__ graph, const float* __restrict__ ag_w,
    const float* __restrict__ ag_b)
{
    extern __shared__ float sm[];
    float* zs = sm;
    float* ws = sm + 16*ZSTR;

    const int tid = threadIdx.x;
    const int r0  = blockIdx.x * 16;

    for (int t = tid; t < 16*64; t += 256) {
        int r = t >> 6, q = t & 63;
        float4 v = (q < 32) ? ((const float4*)node)[(r0 + r)*32 + q]
                            : ((const float4*)hidden)[(r0 + r)*32 + (q - 32)];
        *(float4*)&zs[r*ZSTR + q*4] = v;
    }

    const int cg = tid & 31;
    const int rg = tid >> 5;
    const int c0 = cg * 4;
    const int rowb = rg * 2;

    ull av[2][2], ak[2][2];
    {
        ulonglong2 bv = *(const ulonglong2*)&m_b[c0];
        ulonglong2 bk = *(const ulonglong2*)&skip_b[c0];
        #pragma unroll
        for (int rr = 0; rr < 2; ++rr) {
            av[rr][0] = bv.x; av[rr][1] = bv.y;
            ak[rr][0] = bk.x; ak[rr][1] = bk.y;
        }
    }

    for (int kk = 0; kk < 256; kk += 32) {
        __syncthreads();
        for (int t = tid; t < 2048; t += 256) {
            float4 v = (t < 1024) ? ((const float4*)m_w)[kk*32 + t]
                                  : ((const float4*)skip_w)[kk*32 + (t - 1024)];
            ((float4*)ws)[t] = v;
        }
        __syncthreads();
        #pragma unroll
        for (int k = 0; k < 32; ++k) {
            ulonglong2 wv = *(const ulonglong2*)&ws[k*128 + c0];
            ulonglong2 wk = *(const ulonglong2*)&ws[4096 + k*128 + c0];
            #pragma unroll
            for (int rr = 0; rr < 2; ++rr) {
                float z = zs[(rowb + rr)*ZSTR + kk + k];
                ull zz = pack2(z, z);
                av[rr][0] = ffma2(zz, wv.x, av[rr][0]);
                av[rr][1] = ffma2(zz, wv.y, av[rr][1]);
                ak[rr][0] = ffma2(zz, wk.x, ak[rr][0]);
                ak[rr][1] = ffma2(zz, wk.y, ak[rr][1]);
            }
        }
    }
    #pragma unroll
    for (int rr = 0; rr < 2; ++rr) {
        int rowg = r0 + rowb + rr;
        ulonglong2 o;
        o.x = av[rr][0]; o.y = av[rr][1];
        *(ulonglong2*)&g_V[rowg*128 + c0] = o;
        o.x = ak[rr][0]; o.y = ak[rr][1];
        *(ulonglong2*)&g_SKIP[rowg*128 + c0] = o;
    }

    __syncthreads();
    for (int t = tid; t < 2048; t += 256) {
        ws[t] = a1_w[t];
        ws[4096 + t] = a2_w[t];
    }
    __syncthreads();
    if (tid < 128) {
        int row = tid >> 3, h = tid & 7;
        float a1a = a1_b[h], a1c = 0.0f, a2a = a2_b[h], a2c = 0.0f;
        const float* zp = &zs[row*ZSTR];
        #pragma unroll 8
        for (int k = 0; k < 128; ++k) {
            float za = zp[k], zb = zp[k + 128];
            a1a = fmaf(za, ws[k*8 + h], a1a);
            a1c = fmaf(zb, ws[(k + 128)*8 + h], a1c);
            a2a = fmaf(za, ws[4096 + k*8 + h], a2a);
            a2c = fmaf(zb, ws[4096 + (k + 128)*8 + h], a2c);
        }
        g_A1[(r0 + row)*8 + h] = a1a + a1c;
        g_A2[(r0 + row)*8 + h] = a2a + a2c;
    } else if (blockIdx.x == 0 && tid < 160) {
        int t = tid - 128;
        int b = t >> 3, h = t & 7;
        float acc = ag_b[h];
        #pragma unroll 8
        for (int k = 0; k < 128; ++k)
            acc = fmaf(graph[b*128 + k], ag_w[k*8 + h], acc);
        g_ATTG[t] = acc;
    }
}

// =====================================================================
// cp.async staging of one (TI x TJ) tile: edge, vals, adj, att2.
// =====================================================================
__device__ __forceinline__ void issue_tile(
    unsigned sb, int buf, int j0g, int b, int i0, int tid,
    const float* __restrict__ edge, const int* __restrict__ adj)
{
    const int bi = b*NN + i0;
    // edge: 4096 x 16B chunks
    #pragma unroll
    for (int k = 0; k < 8; ++k) {
        int id = tid + k*512;
        int i = id >> 7, rr = id & 127;
        int j = rr >> 2, c = rr & 3;
        const float* src = edge + ((size_t)(bi + i)*NN + (j0g + j))*16 + c*4;
        cpa16(sb + (unsigned)(EDGE_OFF(buf) + i*516 + j*16 + c*4)*4u, src);
    }
    // vals: 1024 chunks
    #pragma unroll
    for (int k = 0; k < 2; ++k) {
        int id = tid + k*512;
        int hh = id >> 7, rr = id & 127;
        int j = rr >> 2, d4 = rr & 3;
        const float* src = g_V + (size_t)(b*NN + j0g + j)*128 + hh*16 + d4*4;
        cpa16(sb + (unsigned)(VALS_OFF(buf) + hh*640 + j*20 + d4*4)*4u, src);
    }
    // adj: 256 chunks (4 ints each)
    if (tid < 256) {
        int i = tid >> 3, q = tid & 7;
        const int* src = adj + (size_t)(bi + i)*NN + j0g + q*4;
        cpa16(sb + (unsigned)(ADJ_OFF(buf) + i*36 + q*4)*4u, src);
    }
    // att2: 64 chunks
    if (tid < 64) {
        int j = tid >> 1, hf = tid & 1;
        const float* src = g_A2 + (size_t)(b*NN + j0g + j)*8 + hf*4;
        cpa16(sb + (unsigned)(A2_OFF(buf) + j*8 + hf*4)*4u, src);
    }
}

// =====================================================================
// Kernel C: fused attention. 512 thr, TI=32, TJ=32, 1 CTA/SM, grid 128.
// cp.async double-buffered staging; phase A all-smem; phase B as R5.
// =====================================================================
__global__ __launch_bounds__(512, 1) void gat_attn(
    const float* __restrict__ edge, const int* __restrict__ adj,
    const float* __restrict__ ae_w, const float* __restrict__ ae_b,
    float* __restrict__ out)
{
    extern __shared__ float smf[];
    const unsigned sb = (unsigned)__cvta_generic_to_shared(smf);

    const int tid = threadIdx.x;
    const int b   = blockIdx.x >> 5;
    const int it  = blockIdx.x & 31;
    const int i0  = it * TI;

    // phase A ids
    const int hp    = tid & 3;
    const int qi    = (tid >> 2) & 7;
    const int jbase = (tid >> 5) * 2;
    // phase B ids
    const int h  = tid >> 6;
    const int r  = tid & 63;
    const int ip = r >> 2;
    const int jq = r & 3;

    // ae_w resident in registers (d-pair packed, head-pair hp)
    ull wh0[8], wh1[8];
    #pragma unroll
    for (int q = 0; q < 8; ++q) {
        wh0[q] = pack2(ae_w[(2*q)*8 + 2*hp],     ae_w[(2*q+1)*8 + 2*hp]);
        wh1[q] = pack2(ae_w[(2*q)*8 + 2*hp + 1], ae_w[(2*q+1)*8 + 2*hp + 1]);
    }
    // per-thread base for the 4 i-slots this thread serves in phase A
    ull baseA[4];
    {
        float g0 = g_ATTG[b*8 + 2*hp]     + ae_b[2*hp];
        float g1 = g_ATTG[b*8 + 2*hp + 1] + ae_b[2*hp + 1];
        #pragma unroll
        for (int k = 0; k < 4; ++k) {
            const float* a1p = &g_A1[(size_t)(b*NN + i0 + qi + 8*k)*8 + 2*hp];
            baseA[k] = pack2(a1p[0] + g0, a1p[1] + g1);
        }
    }

    const float CAf = 0.505f * 1.4426950408889634f;
    const float CBf = 0.495f * 1.4426950408889634f;
    const ull CA2    = pack2(CAf, CAf);
    const ull CB2    = pack2(CBf, CBf);
    const ull NEG60  = pack2(-60.0f, -60.0f);
    const ull MAGIC2 = pack2(12582912.0f, 12582912.0f);
    const ull P4     = pack2(0.0096181291f, 0.0096181291f);
    const ull P3     = pack2(0.0555041087f, 0.0555041087f);
    const ull P2     = pack2(0.2402265070f, 0.2402265070f);
    const ull P1     = pack2(0.6931471806f, 0.6931471806f);
    const ull ONE2   = pack2(1.0f, 1.0f);

    ull acc0[8], acc1[8];
    #pragma unroll
    for (int q = 0; q < 8; ++q) { acc0[q] = 0ull; acc1[q] = 0ull; }
    ull s2 = 0ull;

    // prologue: stage tile 0
    issue_tile(sb, 0, 0, b, i0, tid, edge, adj);
    cp_commit();

    for (int jt = 0; jt < NN/TJ; ++jt) {
        const int buf = jt & 1;
        cp_wait0();
        __syncthreads();               // tile jt staged; phase B jt-1 done

        if (jt + 1 < NN/TJ)
            issue_tile(sb, buf ^ 1, (jt + 1)*TJ, b, i0, tid, edge, adj);
        cp_commit();

        // ---- phase A: 8 tasks (i, j, hp) from smem ----
        const float* eb = &smf[EDGE_OFF(buf)];
        const float* a2s = &smf[A2_OFF(buf)];
        const int*   ads = (const int*)&smf[ADJ_OFF(buf)];
        #pragma unroll
        for (int tt = 0; tt < 8; ++tt) {
            const int i = qi + (tt >> 1)*8;
            const int j = jbase + (tt & 1);
            const float* ep = &eb[i*516 + j*16];
            ulonglong2 ea = *(const ulonglong2*)(ep);
            ulonglong2 e1 = *(const ulonglong2*)(ep + 4);
            ulonglong2 e2 = *(const ulonglong2*)(ep + 8);
            ulonglong2 e3 = *(const ulonglong2*)(ep + 12);
            ull a2p = *(const ull*)&a2s[j*8 + 2*hp];
            int adv = ads[i*36 + j];

            ull aA = ffma2(ea.x, wh0[0], 0ull);
            ull aB = ffma2(ea.x, wh1[0], 0ull);
            aA = ffma2(ea.y, wh0[1], aA);  aB = ffma2(ea.y, wh1[1], aB);
            aA = ffma2(e1.x, wh0[2], aA);  aB = ffma2(e1.x, wh1[2], aB);
            aA = ffma2(e1.y, wh0[3], aA);  aB = ffma2(e1.y, wh1[3], aB);
            aA = ffma2(e2.x, wh0[4], aA);  aB = ffma2(e2.x, wh1[4], aB);
            aA = ffma2(e2.y, wh0[5], aA);  aB = ffma2(e2.y, wh1[5], aB);
            aA = ffma2(e3.x, wh0[6], aA);  aB = ffma2(e3.x, wh1[6], aB);
            aA = ffma2(e3.y, wh0[7], aA);  aB = ffma2(e3.y, wh1[7], aB);
            float2 fA = unpack2(aA), fB = unpack2(aB);

            ull t2 = pack2(fA.x + fA.y, fB.x + fB.y);
            t2 = fadd2(t2, baseA[tt >> 1]);
            t2 = fadd2(t2, a2p);
            ull ax = t2 & 0x7fffffff7fffffffULL;
            ull l2 = fmul2(t2, CA2);
            l2 = ffma2(ax, CB2, l2);      // leaky * log2e
            l2 = adv ? l2 : NEG60;        // mask
            float2 lf = unpack2(l2);
            const int tb = (i >> 1)*76 + (i & 1)*36 + j;
            smf[T_OFF + (2*hp)*1216 + tb]       = lf.x;
            smf[T_OFF + (2*hp + 1)*1216 + tb]   = lf.y;
        }

        __syncthreads();               // t_s published

        // ---- phase B ----
        const float* tp = &smf[T_OFF + h*1216 + ip*76];
        const float* vp = &smf[VALS_OFF(buf) + h*640];
        #pragma unroll
        for (int jj = 0; jj < 8; ++jj) {
            const int j = jj*4 + jq;
            ull x2 = pack2(tp[j], tp[36 + j]);
            ull r2 = fadd2(x2, MAGIC2);
            ull rm = fsub2(r2, MAGIC2);
            ull f2 = fsub2(x2, rm);
            unsigned rl = (unsigned)r2, rh = (unsigned)(r2 >> 32);
            float sl = __int_as_float((int)((rl - 0x4B3FFF81u) << 23));
            float sh = __int_as_float((int)((rh - 0x4B3FFF81u) << 23));
            ull p2 = ffma2(P4, f2, P3);
            p2 = ffma2(p2, f2, P2);
            p2 = ffma2(p2, f2, P1);
            p2 = ffma2(p2, f2, ONE2);
            p2 = fmul2(p2, pack2(sl, sh));
            s2 = fadd2(s2, p2);
            float2 pf = unpack2(p2);
            ull pp0 = pack2(pf.x, pf.x);
            ull pp1 = pack2(pf.y, pf.y);
            ulonglong2 va = *(const ulonglong2*)&vp[j*20];
            ulonglong2 vb = *(const ulonglong2*)&vp[j*20 + 4];
            ulonglong2 vc = *(const ulonglong2*)&vp[j*20 + 8];
            ulonglong2 vd = *(const ulonglong2*)&vp[j*20 + 12];
            acc0[0]=ffma2(pp0,va.x,acc0[0]); acc0[1]=ffma2(pp0,va.y,acc0[1]);
            acc0[2]=ffma2(pp0,vb.x,acc0[2]); acc0[3]=ffma2(pp0,vb.y,acc0[3]);
            acc0[4]=ffma2(pp0,vc.x,acc0[4]); acc0[5]=ffma2(pp0,vc.y,acc0[5]);
            acc0[6]=ffma2(pp0,vd.x,acc0[6]); acc0[7]=ffma2(pp0,vd.y,acc0[7]);
            acc1[0]=ffma2(pp1,va.x,acc1[0]); acc1[1]=ffma2(pp1,va.y,acc1[1]);
            acc1[2]=ffma2(pp1,vb.x,acc1[2]); acc1[3]=ffma2(pp1,vb.y,acc1[3]);
            acc1[4]=ffma2(pp1,vc.x,acc1[4]); acc1[5]=ffma2(pp1,vc.y,acc1[5]);
            acc1[6]=ffma2(pp1,vd.x,acc1[6]); acc1[7]=ffma2(pp1,vd.y,acc1[7]);
        }
    }

    // reduce across j-quarters (lane bits 0-1)
    #pragma unroll
    for (int m = 1; m <= 2; m <<= 1) {
        #pragma unroll
        for (int q = 0; q < 8; ++q) {
            acc0[q] = fadd2(acc0[q], shflx2(acc0[q], m));
            acc1[q] = fadd2(acc1[q], shflx2(acc1[q], m));
        }
        s2 = fadd2(s2, shflx2(s2, m));
    }
    if (jq == 0) {
        float2 sf = unpack2(s2);
        float inv0 = 1.0f / sf.x;
        float inv1 = 1.0f / sf.y;
        int r0o = (b*NN + i0 + 2*ip)*128 + h*16;
        #pragma unroll
        for (int q4 = 0; q4 < 4; ++q4) {
            float4 sk = *(const float4*)&g_SKIP[r0o + q4*4];
            float2 u0 = unpack2(acc0[q4*2]), u1 = unpack2(acc0[q4*2 + 1]);
            float4 o;
            o.x = fmaxf(fmaf(u0.x, inv0, sk.x), 0.0f);
            o.y = fmaxf(fmaf(u0.y, inv0, sk.y), 0.0f);
            o.z = fmaxf(fmaf(u1.x, inv0, sk.z), 0.0f);
            o.w = fmaxf(fmaf(u1.y, inv0, sk.w), 0.0f);
            *(float4*)&out[r0o + q4*4] = o;
        }
        int r1o = r0o + 128;
        #pragma unroll
        for (int q4 = 0; q4 < 4; ++q4) {
            float4 sk = *(const float4*)&g_SKIP[r1o + q4*4];
            float2 u0 = unpack2(acc1[q4*2]), u1 = unpack2(acc1[q4*2 + 1]);
            float4 o;
            o.x = fmaxf(fmaf(u0.x, inv1, sk.x), 0.0f);
            o.y = fmaxf(fmaf(u0.y, inv1, sk.y), 0.0f);
            o.z = fmaxf(fmaf(u1.x, inv1, sk.z), 0.0f);
            o.w = fmaxf(fmaf(u1.y, inv1, sk.w), 0.0f);
            *(float4*)&out[r1o + q4*4] = o;
        }
    }
}

// =====================================================================
extern "C" void kernel_launch(void* const* d_in, const int* in_sizes, int n_in,
                              void* d_out, int out_size)
{
    const float* node   = (const float*)d_in[0];
    const float* edge   = (const float*)d_in[1];
    const float* graph  = (const float*)d_in[2];
    const int*   adj    = (const int*)  d_in[3];
    const float* hidden = (const float*)d_in[4];
    const float* m_w    = (const float*)d_in[5];
    const float* m_b    = (const float*)d_in[6];
    const float* skip_w = (const float*)d_in[7];
    const float* skip_b = (const float*)d_in[8];
    const float* a1_w   = (const float*)d_in[9];
    const float* a1_b   = (const float*)d_in[10];
    const float* a2_w   = (const float*)d_in[11];
    const float* a2_b   = (const float*)d_in[12];
    const float* ae_w   = (const float*)d_in[13];
    const float* ae_b   = (const float*)d_in[14];
    const float* ag_w   = (const float*)d_in[15];
    const float* ag_b   = (const float*)d_in[16];
    float* out = (float*)d_out;

    const int prep_smem = (16*ZSTR + 8192) * 4;   // 49408 B
    cudaFuncSetAttribute(gat_prep, cudaFuncAttributeMaxDynamicSharedMemorySize,
                         prep_smem);
    const int attn_smem = SMEM_WORDS * 4;         // 223232 B
    cudaFuncSetAttribute(gat_attn, cudaFuncAttributeMaxDynamicSharedMemorySize,
                         attn_smem);

    gat_prep<<<BN/16, 256, prep_smem>>>(node, hidden, m_w, m_b, skip_w, skip_b,
                                        a1_w, a1_b, a2_w, a2_b,
                                        graph, ag_w, ag_b);
    gat_attn<<<4 * (NN/TI), 512, attn_smem>>>(edge, adj, ae_w, ae_b, out);
}

// round 7
// speedup vs baseline: 1.0635x; 1.0635x over previous
#include <cuda_runtime.h>

#define NN 1024
#define BN 4096
#define NH 8
#define TI 16
#define TJ 16

typedef unsigned long long ull;

// ---- scratch ----
__device__ float g_V[BN*128];
__device__ float g_SKIP[BN*128];
__device__ float g_A1[BN*NH];
__device__ float g_A2[BN*NH];
__device__ float g_ATTG[4*NH];

// ---- packed f32x2 helpers ----
__device__ __forceinline__ ull ffma2(ull a, ull b, ull c) {
    ull d; asm("fma.rn.f32x2 %0,%1,%2,%3;" : "=l"(d) : "l"(a), "l"(b), "l"(c)); return d;
}
__device__ __forceinline__ ull fadd2(ull a, ull b) {
    ull d; asm("add.rn.f32x2 %0,%1,%2;" : "=l"(d) : "l"(a), "l"(b)); return d;
}
__device__ __forceinline__ ull fsub2(ull a, ull b) {
    ull d; asm("sub.rn.f32x2 %0,%1,%2;" : "=l"(d) : "l"(a), "l"(b)); return d;
}
__device__ __forceinline__ ull fmul2(ull a, ull b) {
    ull d; asm("mul.rn.f32x2 %0,%1,%2;" : "=l"(d) : "l"(a), "l"(b)); return d;
}
__device__ __forceinline__ ull pack2(float x, float y) {
    ull r; asm("mov.b64 %0,{%1,%2};" : "=l"(r) : "f"(x), "f"(y)); return r;
}
__device__ __forceinline__ float2 unpack2(ull v) {
    float2 r; asm("mov.b64 {%0,%1},%2;" : "=f"(r.x), "=f"(r.y) : "l"(v)); return r;
}
__device__ __forceinline__ ull shflx2(ull v, int m) {
    unsigned lo = (unsigned)v, hi = (unsigned)(v >> 32);
    lo = __shfl_xor_sync(0xffffffffu, lo, m);
    hi = __shfl_xor_sync(0xffffffffu, hi, m);
    return ((ull)hi << 32) | (ull)lo;
}

// ---- cp.async ----
__device__ __forceinline__ void cpa16(unsigned dst, const void* src) {
    asm volatile("cp.async.cg.shared.global [%0], [%1], 16;" :: "r"(dst), "l"(src));
}
__device__ __forceinline__ void cp_commit() {
    asm volatile("cp.async.commit_group;" ::: "memory");
}
__device__ __forceinline__ void cp_wait0() {
    asm volatile("cp.async.wait_group 0;" ::: "memory");
}

// ---- attn smem layout (float words) ----
// edge: [i]*324 + [j]*20 + d          per buf 16*324 = 5184
// vals: [h]*324 + [j]*20 + d          per buf 8*324  = 2592
// t:    [h]*292 + [ip]*36 + [io]*17 + [j]   size 8*292 = 2336 (single buf)
// adj:  [i]*20 + [j] (ints)           per buf 320
// a2:   [j]*8 + [h]                   per buf 128
#define EDGE_OFF(buf) ((buf) ? 5184 : 0)
#define VALS_OFF(buf) ((buf) ? 12960 : 10368)
#define T_OFF         15552
#define ADJ_OFF(buf)  ((buf) ? 18208 : 17888)
#define A2_OFF(buf)   ((buf) ? 18656 : 18528)
#define SMEM_WORDS    18784                    // 75136 bytes

// =====================================================================
// Kernel A: per-node GEMMs (unchanged from R6).
// =====================================================================
#define ZSTR 260
__global__ __launch_bounds__(256, 3) void gat_prep(
    const float* __restrict__ node, const float* __restrict__ hidden,
    const float* __restrict__ m_w,  const float* __restrict__ m_b,
    const float* __restrict__ skip_w, const float* __restrict__ skip_b,
    const float* __restrict__ a1_w, const float* __restrict__ a1_b,
    const float* __restrict__ a2_w, const float* __restrict__ a2_b,
    const float* __restrict__ graph, const float* __restrict__ ag_w,
    const float* __restrict__ ag_b)
{
    extern __shared__ float sm[];
    float* zs = sm;
    float* ws = sm + 16*ZSTR;

    const int tid = threadIdx.x;
    const int r0  = blockIdx.x * 16;

    for (int t = tid; t < 16*64; t += 256) {
        int r = t >> 6, q = t & 63;
        float4 v = (q < 32) ? ((const float4*)node)[(r0 + r)*32 + q]
                            : ((const float4*)hidden)[(r0 + r)*32 + (q - 32)];
        *(float4*)&zs[r*ZSTR + q*4] = v;
    }

    const int cg = tid & 31;
    const int rg = tid >> 5;
    const int c0 = cg * 4;
    const int rowb = rg * 2;

    ull av[2][2], ak[2][2];
    {
        ulonglong2 bv = *(const ulonglong2*)&m_b[c0];
        ulonglong2 bk = *(const ulonglong2*)&skip_b[c0];
        #pragma unroll
        for (int rr = 0; rr < 2; ++rr) {
            av[rr][0] = bv.x; av[rr][1] = bv.y;
            ak[rr][0] = bk.x; ak[rr][1] = bk.y;
        }
    }

    for (int kk = 0; kk < 256; kk += 32) {
        __syncthreads();
        for (int t = tid; t < 2048; t += 256) {
            float4 v = (t < 1024) ? ((const float4*)m_w)[kk*32 + t]
                                  : ((const float4*)skip_w)[kk*32 + (t - 1024)];
            ((float4*)ws)[t] = v;
        }
        __syncthreads();
        #pragma unroll
        for (int k = 0; k < 32; ++k) {
            ulonglong2 wv = *(const ulonglong2*)&ws[k*128 + c0];
            ulonglong2 wk = *(const ulonglong2*)&ws[4096 + k*128 + c0];
            #pragma unroll
            for (int rr = 0; rr < 2; ++rr) {
                float z = zs[(rowb + rr)*ZSTR + kk + k];
                ull zz = pack2(z, z);
                av[rr][0] = ffma2(zz, wv.x, av[rr][0]);
                av[rr][1] = ffma2(zz, wv.y, av[rr][1]);
                ak[rr][0] = ffma2(zz, wk.x, ak[rr][0]);
                ak[rr][1] = ffma2(zz, wk.y, ak[rr][1]);
            }
        }
    }
    #pragma unroll
    for (int rr = 0; rr < 2; ++rr) {
        int rowg = r0 + rowb + rr;
        ulonglong2 o;
        o.x = av[rr][0]; o.y = av[rr][1];
        *(ulonglong2*)&g_V[rowg*128 + c0] = o;
        o.x = ak[rr][0]; o.y = ak[rr][1];
        *(ulonglong2*)&g_SKIP[rowg*128 + c0] = o;
    }

    __syncthreads();
    for (int t = tid; t < 2048; t += 256) {
        ws[t] = a1_w[t];
        ws[4096 + t] = a2_w[t];
    }
    __syncthreads();
    if (tid < 128) {
        int row = tid >> 3, h = tid & 7;
        float a1a = a1_b[h], a1c = 0.0f, a2a = a2_b[h], a2c = 0.0f;
        const float* zp = &zs[row*ZSTR];
        #pragma unroll 8
        for (int k = 0; k < 128; ++k) {
            float za = zp[k], zb = zp[k + 128];
            a1a = fmaf(za, ws[k*8 + h], a1a);
            a1c = fmaf(zb, ws[(k + 128)*8 + h], a1c);
            a2a = fmaf(za, ws[4096 + k*8 + h], a2a);
            a2c = fmaf(zb, ws[4096 + (k + 128)*8 + h], a2c);
        }
        g_A1[(r0 + row)*8 + h] = a1a + a1c;
        g_A2[(r0 + row)*8 + h] = a2a + a2c;
    } else if (blockIdx.x == 0 && tid < 160) {
        int t = tid - 128;
        int b = t >> 3, h = t & 7;
        float acc = ag_b[h];
        #pragma unroll 8
        for (int k = 0; k < 128; ++k)
            acc = fmaf(graph[b*128 + k], ag_w[k*8 + h], acc);
        g_ATTG[t] = acc;
    }
}

// =====================================================================
// Kernel C: fused attention. 256 thr, TI=16, TJ=16, 2 CTAs/SM, grid 256.
// =====================================================================
__global__ __launch_bounds__(256, 2) void gat_attn(
    const float* __restrict__ edge, const int* __restrict__ adj,
    const float* __restrict__ ae_w, const float* __restrict__ ae_b,
    float* __restrict__ out)
{
    extern __shared__ float smf[];
    const unsigned sb = (unsigned)__cvta_generic_to_shared(smf);

    const int tid = threadIdx.x;
    const int b   = blockIdx.x >> 6;
    const int it  = blockIdx.x & 63;
    const int i0  = it * TI;
    const int bi  = b*NN + i0;

    // phase A ids: warp w, lane = (jl, hp)
    const int w  = tid >> 5;
    const int hp = tid & 3;
    const int jl = (tid >> 2) & 7;
    // phase B ids: warp = h
    const int h  = w;
    const int rB = tid & 31;
    const int ip = rB >> 2;
    const int jq = rB & 3;

    // ae_w in registers (d-pair packed) for heads 2hp, 2hp+1
    ull wh0[8], wh1[8];
    #pragma unroll
    for (int q = 0; q < 8; ++q) {
        wh0[q] = pack2(ae_w[(2*q)*8 + 2*hp],     ae_w[(2*q+1)*8 + 2*hp]);
        wh1[q] = pack2(ae_w[(2*q)*8 + 2*hp + 1], ae_w[(2*q+1)*8 + 2*hp + 1]);
    }
    // per-thread base for i = w + 8*ih
    ull baseA[2];
    {
        float g0 = g_ATTG[b*8 + 2*hp]     + ae_b[2*hp];
        float g1 = g_ATTG[b*8 + 2*hp + 1] + ae_b[2*hp + 1];
        #pragma unroll
        for (int ih = 0; ih < 2; ++ih) {
            const float* a1p = &g_A1[(size_t)(bi + w + 8*ih)*8 + 2*hp];
            baseA[ih] = pack2(a1p[0] + g0, a1p[1] + g1);
        }
    }

    const float CAf = 0.505f * 1.4426950408889634f;
    const float CBf = 0.495f * 1.4426950408889634f;
    const ull CA2    = pack2(CAf, CAf);
    const ull CB2    = pack2(CBf, CBf);
    const ull NEG60  = pack2(-60.0f, -60.0f);
    const ull MAGIC2 = pack2(12582912.0f, 12582912.0f);
    const ull P4     = pack2(0.0096181291f, 0.0096181291f);
    const ull P3     = pack2(0.0555041087f, 0.0555041087f);
    const ull P2     = pack2(0.2402265070f, 0.2402265070f);
    const ull P1     = pack2(0.6931471806f, 0.6931471806f);
    const ull ONE2   = pack2(1.0f, 1.0f);

    ull acc0[8], acc1[8];
    #pragma unroll
    for (int q = 0; q < 8; ++q) { acc0[q] = 0ull; acc1[q] = 0ull; }
    ull s2 = 0ull;

    // ---- loop-carried cp.async source pointers ----
    // edge: 4 chunks, id = tid + 256k -> i = id>>6, j = (id&63)>>2, c = id&3
    const float* e_src[4];
    unsigned     e_dst[4];
    #pragma unroll
    for (int k = 0; k < 4; ++k) {
        int id = tid + 256*k;
        int i = id >> 6, rr = id & 63;
        int j = rr >> 2, c = rr & 3;
        e_src[k] = edge + ((size_t)(bi + i)*NN + j)*16 + c*4;
        e_dst[k] = (unsigned)(i*324 + j*20 + c*4)*4u;
    }
    const float* v_src[2];
    unsigned     v_dst[2];
    #pragma unroll
    for (int k = 0; k < 2; ++k) {
        int id = tid + 256*k;
        int hh = id >> 6, rr = id & 63;
        int j = rr >> 2, d4 = rr & 3;
        v_src[k] = g_V + (size_t)(b*NN + j)*128 + hh*16 + d4*4;
        v_dst[k] = (unsigned)(hh*324 + j*20 + d4*4)*4u;
    }
    const int*   adj_src = adj + (size_t)(bi + (tid >> 2))*NN + (tid & 3)*4;
    const unsigned adj_dst = (unsigned)((tid >> 2)*20 + (tid & 3)*4)*4u;
    const float* a2_src = g_A2 + (size_t)(b*NN + (tid >> 1))*8 + (tid & 1)*4;
    const unsigned a2_dst = (unsigned)((tid >> 1)*8 + (tid & 1)*4)*4u;

    // prologue: stage tile 0
    {
        unsigned eb = sb + (unsigned)EDGE_OFF(0)*4u;
        unsigned vb = sb + (unsigned)VALS_OFF(0)*4u;
        #pragma unroll
        for (int k = 0; k < 4; ++k) cpa16(eb + e_dst[k], e_src[k]);
        #pragma unroll
        for (int k = 0; k < 2; ++k) cpa16(vb + v_dst[k], v_src[k]);
        if (tid < 64) cpa16(sb + (unsigned)ADJ_OFF(0)*4u + adj_dst, adj_src);
        if (tid < 32) cpa16(sb + (unsigned)A2_OFF(0)*4u + a2_dst, a2_src);
        #pragma unroll
        for (int k = 0; k < 4; ++k) e_src[k] += TJ*16;
        #pragma unroll
        for (int k = 0; k < 2; ++k) v_src[k] += TJ*128;
        adj_src += TJ;
        a2_src  += TJ*8;
    }
    cp_commit();

    for (int jt = 0; jt < NN/TJ; ++jt) {
        const int buf = jt & 1;
        cp_wait0();
        __syncthreads();               // tile jt staged; phase B jt-1 done

        if (jt + 1 < NN/TJ) {
            unsigned eb = sb + (unsigned)EDGE_OFF(buf ^ 1)*4u;
            unsigned vb = sb + (unsigned)VALS_OFF(buf ^ 1)*4u;
            #pragma unroll
            for (int k = 0; k < 4; ++k) cpa16(eb + e_dst[k], e_src[k]);
            #pragma unroll
            for (int k = 0; k < 2; ++k) cpa16(vb + v_dst[k], v_src[k]);
            if (tid < 64) cpa16(sb + (unsigned)ADJ_OFF(buf ^ 1)*4u + adj_dst, adj_src);
            if (tid < 32) cpa16(sb + (unsigned)A2_OFF(buf ^ 1)*4u + a2_dst, a2_src);
            #pragma unroll
            for (int k = 0; k < 4; ++k) e_src[k] += TJ*16;
            #pragma unroll
            for (int k = 0; k < 2; ++k) v_src[k] += TJ*128;
            adj_src += TJ;
            a2_src  += TJ*8;
        }
        cp_commit();

        // ---- phase A: 4 tasks (ih, jh) ----
        const float* ebf = &smf[EDGE_OFF(buf)];
        const float* a2s = &smf[A2_OFF(buf)];
        const int*   ads = (const int*)&smf[ADJ_OFF(buf)];
        #pragma unroll
        for (int tt = 0; tt < 4; ++tt) {
            const int ih = tt >> 1, jh = tt & 1;
            const int i = w + 8*ih;
            const int j = jl + 8*jh;
            const float* ep = &ebf[i*324 + j*20];
            ulonglong2 ea = *(const ulonglong2*)(ep);
            ulonglong2 e1 = *(const ulonglong2*)(ep + 4);
            ulonglong2 e2 = *(const ulonglong2*)(ep + 8);
            ulonglong2 e3 = *(const ulonglong2*)(ep + 12);
            ull a2p = *(const ull*)&a2s[j*8 + 2*hp];
            int adv = ads[i*20 + j];

            ull aA = ffma2(ea.x, wh0[0], 0ull);
            ull aB = ffma2(ea.x, wh1[0], 0ull);
            aA = ffma2(ea.y, wh0[1], aA);  aB = ffma2(ea.y, wh1[1], aB);
            aA = ffma2(e1.x, wh0[2], aA);  aB = ffma2(e1.x, wh1[2], aB);
            aA = ffma2(e1.y, wh0[3], aA);  aB = ffma2(e1.y, wh1[3], aB);
            aA = ffma2(e2.x, wh0[4], aA);  aB = ffma2(e2.x, wh1[4], aB);
            aA = ffma2(e2.y, wh0[5], aA);  aB = ffma2(e2.y, wh1[5], aB);
            aA = ffma2(e3.x, wh0[6], aA);  aB = ffma2(e3.x, wh1[6], aB);
            aA = ffma2(e3.y, wh0[7], aA);  aB = ffma2(e3.y, wh1[7], aB);
            float2 fA = unpack2(aA), fB = unpack2(aB);

            ull t2 = pack2(fA.x + fA.y, fB.x + fB.y);
            t2 = fadd2(t2, baseA[ih]);
            t2 = fadd2(t2, a2p);
            ull ax = t2 & 0x7fffffff7fffffffULL;
            ull l2 = fmul2(t2, CA2);
            l2 = ffma2(ax, CB2, l2);
            l2 = adv ? l2 : NEG60;
            float2 lf = unpack2(l2);
            const int tb = (i >> 1)*36 + (i & 1)*17 + j;
            smf[T_OFF + (2*hp)*292 + tb]     = lf.x;
            smf[T_OFF + (2*hp + 1)*292 + tb] = lf.y;
        }

        __syncthreads();               // t published

        // ---- phase B ----
        const float* tp = &smf[T_OFF + h*292 + ip*36];
        const float* vp = &smf[VALS_OFF(buf) + h*324];
        #pragma unroll
        for (int jj = 0; jj < 4; ++jj) {
            const int j = jj*4 + jq;
            ull x2 = pack2(tp[j], tp[17 + j]);
            ull r2 = fadd2(x2, MAGIC2);
            ull rm = fsub2(r2, MAGIC2);
            ull f2 = fsub2(x2, rm);
            unsigned rl = (unsigned)r2, rh = (unsigned)(r2 >> 32);
            float sl = __int_as_float((int)((rl - 0x4B3FFF81u) << 23));
            float sh = __int_as_float((int)((rh - 0x4B3FFF81u) << 23));
            ull p2 = ffma2(P4, f2, P3);
            p2 = ffma2(p2, f2, P2);
            p2 = ffma2(p2, f2, P1);
            p2 = ffma2(p2, f2, ONE2);
            p2 = fmul2(p2, pack2(sl, sh));
            s2 = fadd2(s2, p2);
            float2 pf = unpack2(p2);
            ull pp0 = pack2(pf.x, pf.x);
            ull pp1 = pack2(pf.y, pf.y);
            ulonglong2 va = *(const ulonglong2*)&vp[j*20];
            ulonglong2 vb = *(const ulonglong2*)&vp[j*20 + 4];
            ulonglong2 vc = *(const ulonglong2*)&vp[j*20 + 8];
            ulonglong2 vd = *(const ulonglong2*)&vp[j*20 + 12];
            acc0[0]=ffma2(pp0,va.x,acc0[0]); acc0[1]=ffma2(pp0,va.y,acc0[1]);
            acc0[2]=ffma2(pp0,vb.x,acc0[2]); acc0[3]=ffma2(pp0,vb.y,acc0[3]);
            acc0[4]=ffma2(pp0,vc.x,acc0[4]); acc0[5]=ffma2(pp0,vc.y,acc0[5]);
            acc0[6]=ffma2(pp0,vd.x,acc0[6]); acc0[7]=ffma2(pp0,vd.y,acc0[7]);
            acc1[0]=ffma2(pp1,va.x,acc1[0]); acc1[1]=ffma2(pp1,va.y,acc1[1]);
            acc1[2]=ffma2(pp1,vb.x,acc1[2]); acc1[3]=ffma2(pp1,vb.y,acc1[3]);
            acc1[4]=ffma2(pp1,vc.x,acc1[4]); acc1[5]=ffma2(pp1,vc.y,acc1[5]);
            acc1[6]=ffma2(pp1,vd.x,acc1[6]); acc1[7]=ffma2(pp1,vd.y,acc1[7]);
        }
    }

    // reduce across j-quarters (lane bits 0-1)
    #pragma unroll
    for (int m = 1; m <= 2; m <<= 1) {
        #pragma unroll
        for (int q = 0; q < 8; ++q) {
            acc0[q] = fadd2(acc0[q], shflx2(acc0[q], m));
            acc1[q] = fadd2(acc1[q], shflx2(acc1[q], m));
        }
        s2 = fadd2(s2, shflx2(s2, m));
    }
    if (jq == 0) {
        float2 sf = unpack2(s2);
        float inv0 = 1.0f / sf.x;
        float inv1 = 1.0f / sf.y;
        int r0o = (bi + 2*ip)*128 + h*16;
        #pragma unroll
        for (int q4 = 0; q4 < 4; ++q4) {
            float4 sk = *(const float4*)&g_SKIP[r0o + q4*4];
            float2 u0 = unpack2(acc0[q4*2]), u1 = unpack2(acc0[q4*2 + 1]);
            float4 o;
            o.x = fmaxf(fmaf(u0.x, inv0, sk.x), 0.0f);
            o.y = fmaxf(fmaf(u0.y, inv0, sk.y), 0.0f);
            o.z = fmaxf(fmaf(u1.x, inv0, sk.z), 0.0f);
            o.w = fmaxf(fmaf(u1.y, inv0, sk.w), 0.0f);
            *(float4*)&out[r0o + q4*4] = o;
        }
        int r1o = r0o + 128;
        #pragma unroll
        for (int q4 = 0; q4 < 4; ++q4) {
            float4 sk = *(const float4*)&g_SKIP[r1o + q4*4];
            float2 u0 = unpack2(acc1[q4*2]), u1 = unpack2(acc1[q4*2 + 1]);
            float4 o;
            o.x = fmaxf(fmaf(u0.x, inv1, sk.x), 0.0f);
            o.y = fmaxf(fmaf(u0.y, inv1, sk.y), 0.0f);
            o.z = fmaxf(fmaf(u1.x, inv1, sk.z), 0.0f);
            o.w = fmaxf(fmaf(u1.y, inv1, sk.w), 0.0f);
            *(float4*)&out[r1o + q4*4] = o;
        }
    }
}

// =====================================================================
extern "C" void kernel_launch(void* const* d_in, const int* in_sizes, int n_in,
                              void* d_out, int out_size)
{
    const float* node   = (const float*)d_in[0];
    const float* edge   = (const float*)d_in[1];
    const float* graph  = (const float*)d_in[2];
    const int*   adj    = (const int*)  d_in[3];
    const float* hidden = (const float*)d_in[4];
    const float* m_w    = (const float*)d_in[5];
    const float* m_b    = (const float*)d_in[6];
    const float* skip_w = (const float*)d_in[7];
    const float* skip_b = (const float*)d_in[8];
    const float* a1_w   = (const float*)d_in[9];
    const float* a1_b   = (const float*)d_in[10];
    const float* a2_w   = (const float*)d_in[11];
    const float* a2_b   = (const float*)d_in[12];
    const float* ae_w   = (const float*)d_in[13];
    const float* ae_b   = (const float*)d_in[14];
    const float* ag_w   = (const float*)d_in[15];
    const float* ag_b   = (const float*)d_in[16];
    float* out = (float*)d_out;

    const int prep_smem = (16*ZSTR + 8192) * 4;   // 49408 B
    cudaFuncSetAttribute(gat_prep, cudaFuncAttributeMaxDynamicSharedMemorySize,
                         prep_smem);
    const int attn_smem = SMEM_WORDS * 4;         // 75136 B
    cudaFuncSetAttribute(gat_attn, cudaFuncAttributeMaxDynamicSharedMemorySize,
                         attn_smem);

    gat_prep<<<BN/16, 256, prep_smem>>>(node, hidden, m_w, m_b, skip_w, skip_b,
                                        a1_w, a1_b, a2_w, a2_b,
                                        graph, ag_w, ag_b);
    gat_attn<<<4 * (NN/TI), 256, attn_smem>>>(edge, adj, ae_w, ae_b, out);
}